// round 15
// baseline (speedup 1.0000x reference)
#include <cuda_runtime.h>
#include <math.h>

#define B_   128
#define L_   512
#define NH   1024
#define TPB  512
#define ROWB 4096            // bytes per weight row (NH * 4)
#define DTc  0.05f

// per-block partial stats: [thrf, tlif, vs, vsq, ls, lsq, pad, pad]
__device__ float g_partials[B_ * 8];

__device__ __forceinline__ float fadd(float a, float b){ return __fadd_rn(a,b); }
__device__ __forceinline__ float fmul(float a, float b){ return __fmul_rn(a,b); }
__device__ __forceinline__ float fsub(float a, float b){ return __fsub_rn(a,b); }
__device__ __forceinline__ float ffma(float a, float b, float c){ return __fmaf_rn(a,b,c); }

// deterministic block reduction for 16 warps; result valid on thread 0
__device__ __forceinline__ float block_reduce16(float v, int wid, int lane, float* redf)
{
    #pragma unroll
    for (int o = 16; o > 0; o >>= 1) v += __shfl_down_sync(0xffffffffu, v, o);
    if (lane == 0) redf[wid] = v;
    __syncthreads();
    float r = 0.f;
    if (wid == 0) {
        r = (lane < 16) ? redf[lane] : 0.f;
        #pragma unroll
        for (int o = 8; o > 0; o >>= 1) r += __shfl_down_sync(0xffffffffu, r, o);
    }
    __syncthreads();
    return r;
}

// sparse row-gather: list holds BYTE offsets (k*4096); base includes this
// thread's column offset. Tail handled as ONE 16-wide predicated burst so all
// row loads issue in a single wave (one L2 round-trip instead of 2-4).
__device__ __forceinline__ float2 gather_flat(
    const char* __restrict__ base,
    const int* __restrict__ list,   // 16-byte aligned, capacity NH ints
    int cnt)
{
    float2 a0 = {0,0}, a1 = {0,0}, a2 = {0,0}, a3 = {0,0};
    int i = 0;
    for (; i + 16 <= cnt; i += 16) {
        #pragma unroll
        for (int u = 0; u < 4; u++) {
            int4 k = *reinterpret_cast<const int4*>(list + i + 4 * u);
            float2 r0 = __ldg(reinterpret_cast<const float2*>(base + k.x));
            float2 r1 = __ldg(reinterpret_cast<const float2*>(base + k.y));
            float2 r2 = __ldg(reinterpret_cast<const float2*>(base + k.z));
            float2 r3 = __ldg(reinterpret_cast<const float2*>(base + k.w));
            a0.x += r0.x; a0.y += r0.y;  a1.x += r1.x; a1.y += r1.y;
            a2.x += r2.x; a2.y += r2.y;  a3.x += r3.x; a3.y += r3.y;
        }
    }
    const int r = cnt - i;
    if (r > 0) {
        // indices i..i+15 are in-bounds reads (capacity NH); entries >= r are
        // stale-but-valid offsets, predicated off below.
        int4 k0 = *reinterpret_cast<const int4*>(list + i);
        int4 k1 = *reinterpret_cast<const int4*>(list + i + 4);
        int4 k2 = *reinterpret_cast<const int4*>(list + i + 8);
        int4 k3 = *reinterpret_cast<const int4*>(list + i + 12);
#define ACC(P, KO, AC)                                                        \
        if (r > (P)) {                                                        \
            float2 t = __ldg(reinterpret_cast<const float2*>(base + (KO)));   \
            AC.x += t.x; AC.y += t.y;                                         \
        }
        ACC(0,  k0.x, a0)  ACC(1,  k0.y, a1)  ACC(2,  k0.z, a2)  ACC(3,  k0.w, a3)
        ACC(4,  k1.x, a0)  ACC(5,  k1.y, a1)  ACC(6,  k1.z, a2)  ACC(7,  k1.w, a3)
        ACC(8,  k2.x, a0)  ACC(9,  k2.y, a1)  ACC(10, k2.z, a2)  ACC(11, k2.w, a3)
        ACC(12, k3.x, a0)  ACC(13, k3.y, a1)  ACC(14, k3.z, a2)  ACC(15, k3.w, a3)
#undef ACC
    }
    float2 g;
    g.x = fadd(fadd(a0.x, a1.x), fadd(a2.x, a3.x));
    g.y = fadd(fadd(a0.y, a1.y), fadd(a2.y, a3.y));
    return g;
}

__global__ __launch_bounds__(TPB, 1) void coesn_kernel(
    const float* __restrict__ x,        // (B, L, 1)
    const float* __restrict__ x2h,      // (1, NH)
    const float* __restrict__ h2h,      // (NH, NH) row-major [k][j]
    const float* __restrict__ bias,     // (NH)
    const float* __restrict__ lif2hrf,  // (NH, NH)
    const float* __restrict__ gamma,    // (NH)
    const float* __restrict__ eps,      // (NH)
    const float* __restrict__ sgain,    // scalar
    float* __restrict__ out)            // (B*NH hy) ++ 7 scalars
{
    const int b    = blockIdx.x;
    const int j    = threadIdx.x;          // owns neurons 2j, 2j+1
    const int wid  = j >> 5;               // 0..15
    const int lane = j & 31;
    const unsigned lmask = (1u << lane) - 1u;

    __shared__ float xs[L_];
    __shared__ __align__(16) int list_s[NH];  // HRF spike row byte-offsets (next step)
    __shared__ __align__(16) int list_l[NH];  // LIF spike row byte-offsets (same step)
    __shared__ int  cntS0, cntS1, cntL0, cntL1;   // parity-alternating counters
    __shared__ float redf[16];

    xs[j] = x[b * L_ + j];                 // TPB == L_
    if (j == 0) { cntS0 = 0; cntS1 = 0; cntL0 = 0; cntL1 = 0; }

    float2 rw = ((const float2*)x2h)[j];
    float2 rb = ((const float2*)bias)[j];
    float2 rgn, ren;                       // pre-negated gamma / epsilon
    {
        float2 g2 = ((const float2*)gamma)[j];
        float2 e2 = ((const float2*)eps)[j];
        rgn.x = -g2.x; rgn.y = -g2.y;
        ren.x = -e2.x; ren.y = -e2.y;
    }
    const float rs   = sgain[0];
    const float refd = 0.81873075307798182f;   // exp(-DT/TAU_REF) = exp(-0.2)
    const float vdec = ffma(-0.05f, DTc, 1.0f); // 1 - DT/20  (v' = v*vdec + DT*cur)
    const int off0 = j * (2 * ROWB);           // byte offset of row 2j
    const int off1 = off0 + ROWB;              // byte offset of row 2j+1

    float hy0=0.f, hy1=0.f, hz0=0.f, hz1=0.f, rf0=0.f, rf1=0.f, v0=0.f, v1=0.f;
    float vs = 0.f, vsq = 0.f, ls = 0.f, lsq = 0.f;
    int thrf = 0, tlif = 0;

    const char* hp = (const char*)h2h     + j * 8;   // column offset (float2)
    const char* lp = (const char*)lif2hrf + j * 8;

    __syncthreads();

#define STEP_BODY(CNT_S_CONS, CNT_L_PUB, CNT_S_RST, CNT_L_CONS, CNT_S_PUB, CNT_L_RST, T) \
    {                                                                                    \
        const float xt = xs[T];                                                          \
        /* phase 1: cur = x*x2h + s@h2h + bias ; LIF update */                           \
        float2 gem = gather_flat(hp, list_s, CNT_S_CONS);                                \
        float cur0 = ffma(xt, rw.x, fadd(gem.x, rb.x));                                  \
        float cur1 = ffma(xt, rw.y, fadd(gem.y, rb.y));                                  \
        v0 = ffma(DTc, cur0, fmul(v0, vdec));                                            \
        v1 = ffma(DTc, cur1, fmul(v1, vdec));                                            \
        bool lspk0 = (v0 > 1.0f), lspk1 = (v1 > 1.0f);                                   \
        if (lspk0) v0 = fsub(v0, 1.0f);                                                  \
        if (lspk1) v1 = fsub(v1, 1.0f);                                                  \
        tlif += (lspk0 ? 1 : 0) + (lspk1 ? 1 : 0);                                       \
        vs  = fadd(fadd(vs, v0), v1);                                                    \
        vsq = fadd(fadd(vsq, fmul(v0, v0)), fmul(v1, v1));                               \
        {                                                                                \
            unsigned b0 = __ballot_sync(0xffffffffu, lspk0);                             \
            unsigned b1 = __ballot_sync(0xffffffffu, lspk1);                             \
            if (b0 | b1) {   /* warp-uniform: skip whole publish if no spikes */         \
                int wn = __popc(b0) + __popc(b1);                                        \
                int base = 0;                                                            \
                if (lane == 0) base = atomicAdd(&CNT_L_PUB, wn);                         \
                base = __shfl_sync(0xffffffffu, base, 0);                                \
                int pre = base + __popc(b0 & lmask) + __popc(b1 & lmask);                \
                if (lspk0) list_l[pre] = off0;                                           \
                if (lspk1) list_l[pre + (lspk0 ? 1 : 0)] = off1;                         \
            }                                                                            \
            if (wid == 15) { if (lane == 0) CNT_S_RST = 0; }                             \
        }                                                                                \
        __syncthreads();                                                                 \
        /* phase 2: l2h = lif_s @ lif2hrf ; HRF update */                                \
        float2 l2h = gather_flat(lp, list_l, CNT_L_CONS);                                \
        ls  = fadd(fadd(ls, l2h.x), l2h.y);                                              \
        lsq = fadd(fadd(lsq, fmul(l2h.x, l2h.x)), fmul(l2h.y, l2h.y));                   \
        float dd0 = ffma(ren.x, hz0, ffma(rgn.x, hy0, fmul(rs, l2h.x)));                 \
        float dd1 = ffma(ren.y, hz1, ffma(rgn.y, hy1, fmul(rs, l2h.y)));                 \
        hz0 = ffma(DTc, dd0, hz0);                                                       \
        hz1 = ffma(DTc, dd1, hz1);                                                       \
        hy0 = ffma(DTc, hz0, hy0);                                                       \
        hy1 = ffma(DTc, hz1, hy1);                                                       \
        bool spk0 = (fsub(fsub(hy0, 1.0f), rf0) > 0.0f);                                 \
        bool spk1 = (fsub(fsub(hy1, 1.0f), rf1) > 0.0f);                                 \
        rf0 = ffma(rf0, refd, spk0 ? 1.0f : 0.0f);                                       \
        rf1 = ffma(rf1, refd, spk1 ? 1.0f : 0.0f);                                       \
        thrf += (spk0 ? 1 : 0) + (spk1 ? 1 : 0);                                         \
        {                                                                                \
            unsigned c0 = __ballot_sync(0xffffffffu, spk0);                              \
            unsigned c1 = __ballot_sync(0xffffffffu, spk1);                              \
            if (c0 | c1) {                                                               \
                int wn = __popc(c0) + __popc(c1);                                        \
                int base = 0;                                                            \
                if (lane == 0) base = atomicAdd(&CNT_S_PUB, wn);                         \
                base = __shfl_sync(0xffffffffu, base, 0);                                \
                int pre = base + __popc(c0 & lmask) + __popc(c1 & lmask);                \
                if (spk0) list_s[pre] = off0;                                            \
                if (spk1) list_s[pre + (spk0 ? 1 : 0)] = off1;                           \
            }                                                                            \
            if (wid == 15) { if (lane == 0) CNT_L_RST = 0; }                             \
        }                                                                                \
        __syncthreads();                                                                 \
    }

    for (int t = 0; t < L_; t += 2) {
        // even step (p=0,q=1)
        STEP_BODY(cntS1, cntL0, cntS0, cntL0, cntS0, cntL1, t)
        // odd step  (p=1,q=0)
        STEP_BODY(cntS0, cntL1, cntS1, cntL1, cntS1, cntL0, t + 1)
    }
#undef STEP_BODY

    // output hy
    {
        float2 o; o.x = hy0; o.y = hy1;
        ((float2*)(out + b * NH))[j] = o;
    }

    // ---------- block-level stat reductions (deterministic trees) ----------
    float r;
    r = block_reduce16((float)thrf, wid, lane, redf); if (j == 0) g_partials[b*8 + 0] = r;
    r = block_reduce16((float)tlif, wid, lane, redf); if (j == 0) g_partials[b*8 + 1] = r;
    r = block_reduce16(vs,  wid, lane, redf);         if (j == 0) g_partials[b*8 + 2] = r;
    r = block_reduce16(vsq, wid, lane, redf);         if (j == 0) g_partials[b*8 + 3] = r;
    r = block_reduce16(ls,  wid, lane, redf);         if (j == 0) g_partials[b*8 + 4] = r;
    r = block_reduce16(lsq, wid, lane, redf);         if (j == 0) g_partials[b*8 + 5] = r;
}

// parallel, deterministic finalize: 128 threads (one per batch), shuffle trees in double
__global__ void finalize_kernel(float* __restrict__ out)
{
    const int b    = threadIdx.x;          // 0..127
    const int wid  = b >> 5;
    const int lane = b & 31;
    __shared__ double sd[6][4];

    double val[6];
    #pragma unroll
    for (int s = 0; s < 6; s++) val[s] = (double)g_partials[b * 8 + s];

    #pragma unroll
    for (int s = 0; s < 6; s++) {
        double v = val[s];
        #pragma unroll
        for (int o = 16; o > 0; o >>= 1) v += __shfl_down_sync(0xffffffffu, v, o);
        if (lane == 0) sd[s][wid] = v;
    }
    __syncthreads();

    if (b == 0) {
        double tot[6];
        #pragma unroll
        for (int s = 0; s < 6; s++)
            tot[s] = (sd[s][0] + sd[s][1]) + (sd[s][2] + sd[s][3]);
        const double denom = (double)B_ * (double)L_ * (double)NH;
        float r_hrf = (float)(tot[0] / denom);
        float r_lif = (float)(tot[1] / denom);
        float vm    = (float)(tot[2] / denom);
        float vstd  = sqrtf((float)(tot[3] / denom) - vm * vm);
        float lm    = (float)(tot[4] / denom);
        float lstd  = sqrtf((float)(tot[5] / denom) - lm * lm);
        float* sc = out + B_ * NH;
        sc[0] = r_hrf;   // r_total (count_lif_spikes=False)
        sc[1] = r_hrf;
        sc[2] = r_lif;
        sc[3] = vm;
        sc[4] = vstd;
        sc[5] = lm;
        sc[6] = lstd;
    }
}

extern "C" void kernel_launch(void* const* d_in, const int* in_sizes, int n_in,
                              void* d_out, int out_size)
{
    const float* x       = (const float*)d_in[0];
    const float* x2h     = (const float*)d_in[1];
    const float* h2h     = (const float*)d_in[2];
    const float* bias    = (const float*)d_in[3];
    const float* lif2hrf = (const float*)d_in[4];
    const float* gamma   = (const float*)d_in[5];
    const float* eps     = (const float*)d_in[6];
    const float* sg      = (const float*)d_in[7];
    float* out = (float*)d_out;

    coesn_kernel<<<B_, TPB>>>(x, x2h, h2h, bias, lif2hrf, gamma, eps, sg, out);
    finalize_kernel<<<1, 128>>>(out);
}

// round 16
// speedup vs baseline: 1.5551x; 1.5551x over previous
#include <cuda_runtime.h>
#include <math.h>

#define B_   128
#define L_   512
#define NH   1024
#define TPB  512
#define ROWB 4096            // bytes per weight row (NH * 4)
#define DTc  0.05f

// per-block partial stats: [thrf, tlif, vs, vsq, ls, lsq, pad, pad]
__device__ float g_partials[B_ * 8];

__device__ __forceinline__ float fadd(float a, float b){ return __fadd_rn(a,b); }
__device__ __forceinline__ float fmul(float a, float b){ return __fmul_rn(a,b); }
__device__ __forceinline__ float fsub(float a, float b){ return __fsub_rn(a,b); }
__device__ __forceinline__ float ffma(float a, float b, float c){ return __fmaf_rn(a,b,c); }

// deterministic block reduction for 16 warps; result valid on thread 0
__device__ __forceinline__ float block_reduce16(float v, int wid, int lane, float* redf)
{
    #pragma unroll
    for (int o = 16; o > 0; o >>= 1) v += __shfl_down_sync(0xffffffffu, v, o);
    if (lane == 0) redf[wid] = v;
    __syncthreads();
    float r = 0.f;
    if (wid == 0) {
        r = (lane < 16) ? redf[lane] : 0.f;
        #pragma unroll
        for (int o = 8; o > 0; o >>= 1) r += __shfl_down_sync(0xffffffffu, r, o);
    }
    __syncthreads();
    return r;
}

// sparse row-gather: list holds BYTE offsets of rows (k*4096); base already
// includes this thread's column offset. 8-wide main loop (same accumulator
// rotation as the 4-wide loop -> bit-identical FP order, double MLP).
__device__ __forceinline__ float2 gather_rows2(
    const char* __restrict__ base,
    const int* __restrict__ list,   // 16-byte aligned
    int cnt)
{
    float2 a0 = {0,0}, a1 = {0,0}, a2 = {0,0}, a3 = {0,0};
    int i = 0;
    for (; i + 8 <= cnt; i += 8) {
        int4 ka = *reinterpret_cast<const int4*>(list + i);
        int4 kb = *reinterpret_cast<const int4*>(list + i + 4);
        float2 r0 = __ldg(reinterpret_cast<const float2*>(base + ka.x));
        float2 r1 = __ldg(reinterpret_cast<const float2*>(base + ka.y));
        float2 r2 = __ldg(reinterpret_cast<const float2*>(base + ka.z));
        float2 r3 = __ldg(reinterpret_cast<const float2*>(base + ka.w));
        float2 r4 = __ldg(reinterpret_cast<const float2*>(base + kb.x));
        float2 r5 = __ldg(reinterpret_cast<const float2*>(base + kb.y));
        float2 r6 = __ldg(reinterpret_cast<const float2*>(base + kb.z));
        float2 r7 = __ldg(reinterpret_cast<const float2*>(base + kb.w));
        a0.x += r0.x; a0.y += r0.y;  a1.x += r1.x; a1.y += r1.y;
        a2.x += r2.x; a2.y += r2.y;  a3.x += r3.x; a3.y += r3.y;
        a0.x += r4.x; a0.y += r4.y;  a1.x += r5.x; a1.y += r5.y;
        a2.x += r6.x; a2.y += r6.y;  a3.x += r7.x; a3.y += r7.y;
    }
    if (i + 4 <= cnt) {
        int4 k = *reinterpret_cast<const int4*>(list + i);
        float2 r0 = __ldg(reinterpret_cast<const float2*>(base + k.x));
        float2 r1 = __ldg(reinterpret_cast<const float2*>(base + k.y));
        float2 r2 = __ldg(reinterpret_cast<const float2*>(base + k.z));
        float2 r3 = __ldg(reinterpret_cast<const float2*>(base + k.w));
        a0.x += r0.x; a0.y += r0.y;  a1.x += r1.x; a1.y += r1.y;
        a2.x += r2.x; a2.y += r2.y;  a3.x += r3.x; a3.y += r3.y;
        i += 4;
    }
    for (; i < cnt; i++) {
        float2 r = __ldg(reinterpret_cast<const float2*>(base + list[i]));
        a0.x += r.x; a0.y += r.y;
    }
    float2 g;
    g.x = fadd(fadd(a0.x, a1.x), fadd(a2.x, a3.x));
    g.y = fadd(fadd(a0.y, a1.y), fadd(a2.y, a3.y));
    return g;
}

__global__ __launch_bounds__(TPB, 1) void coesn_kernel(
    const float* __restrict__ x,        // (B, L, 1)
    const float* __restrict__ x2h,      // (1, NH)
    const float* __restrict__ h2h,      // (NH, NH) row-major [k][j]
    const float* __restrict__ bias,     // (NH)
    const float* __restrict__ lif2hrf,  // (NH, NH)
    const float* __restrict__ gamma,    // (NH)
    const float* __restrict__ eps,      // (NH)
    const float* __restrict__ sgain,    // scalar
    float* __restrict__ out)            // (B*NH hy) ++ 7 scalars
{
    const int b    = blockIdx.x;
    const int j    = threadIdx.x;          // owns neurons 2j, 2j+1
    const int wid  = j >> 5;               // 0..15
    const int lane = j & 31;
    const unsigned lmask = (1u << lane) - 1u;

    __shared__ float xs[L_];
    __shared__ __align__(16) int list_s[NH];  // HRF spike row byte-offsets (next step)
    __shared__ __align__(16) int list_l[NH];  // LIF spike row byte-offsets (same step)
    __shared__ int  cntS0, cntS1, cntL0, cntL1;   // parity-alternating counters
    __shared__ float redf[16];

    xs[j] = x[b * L_ + j];                 // TPB == L_
    if (j == 0) { cntS0 = 0; cntS1 = 0; cntL0 = 0; cntL1 = 0; }

    float2 rw = ((const float2*)x2h)[j];
    float2 rb = ((const float2*)bias)[j];
    float2 rgn, ren;                       // pre-negated gamma / epsilon
    {
        float2 g2 = ((const float2*)gamma)[j];
        float2 e2 = ((const float2*)eps)[j];
        rgn.x = -g2.x; rgn.y = -g2.y;
        ren.x = -e2.x; ren.y = -e2.y;
    }
    const float rs   = sgain[0];
    const float refd = 0.81873075307798182f;   // exp(-DT/TAU_REF) = exp(-0.2)
    const int off0 = j * (2 * ROWB);           // byte offset of row 2j
    const int off1 = off0 + ROWB;              // byte offset of row 2j+1

    float hy0=0.f, hy1=0.f, hz0=0.f, hz1=0.f, rf0=0.f, rf1=0.f, v0=0.f, v1=0.f;
    float vs = 0.f, vsq = 0.f, ls = 0.f, lsq = 0.f;
    int thrf = 0, tlif = 0;

    const char* hp = (const char*)h2h     + j * 8;   // column offset (float2)
    const char* lp = (const char*)lif2hrf + j * 8;

    __syncthreads();

#define STEP_BODY(CNT_S_CONS, CNT_L_PUB, CNT_S_RST, CNT_L_CONS, CNT_S_PUB, CNT_L_RST, T) \
    {                                                                                    \
        const float xt = xs[T];                                                          \
        /* phase 1: cur = x*x2h + s@h2h + bias ; LIF update */                           \
        float2 gem = gather_rows2(hp, list_s, CNT_S_CONS);                               \
        float cur0 = ffma(xt, rw.x, fadd(gem.x, rb.x));                                  \
        float cur1 = ffma(xt, rw.y, fadd(gem.y, rb.y));                                  \
        v0 = ffma(DTc, fadd(fmul(v0, -0.05f), cur0), v0);                                \
        v1 = ffma(DTc, fadd(fmul(v1, -0.05f), cur1), v1);                                \
        bool lspk0 = (v0 > 1.0f), lspk1 = (v1 > 1.0f);                                   \
        if (lspk0) v0 = fsub(v0, 1.0f);                                                  \
        if (lspk1) v1 = fsub(v1, 1.0f);                                                  \
        tlif += (lspk0 ? 1 : 0) + (lspk1 ? 1 : 0);                                       \
        vs  = fadd(fadd(vs, v0), v1);                                                    \
        vsq = fadd(fadd(vsq, fmul(v0, v0)), fmul(v1, v1));                               \
        {                                                                                \
            unsigned b0 = __ballot_sync(0xffffffffu, lspk0);                             \
            unsigned b1 = __ballot_sync(0xffffffffu, lspk1);                             \
            if (b0 | b1) {   /* warp-uniform: skip whole publish if no spikes */         \
                int wn = __popc(b0) + __popc(b1);                                        \
                int base = 0;                                                            \
                if (lane == 0) base = atomicAdd(&CNT_L_PUB, wn);                         \
                base = __shfl_sync(0xffffffffu, base, 0);                                \
                int pre = base + __popc(b0 & lmask) + __popc(b1 & lmask);                \
                if (lspk0) list_l[pre] = off0;                                           \
                if (lspk1) list_l[pre + (lspk0 ? 1 : 0)] = off1;                         \
            }                                                                            \
            if (wid == 15) { if (lane == 0) CNT_S_RST = 0; }                             \
        }                                                                                \
        __syncthreads();                                                                 \
        /* phase 2: l2h = lif_s @ lif2hrf ; HRF update */                                \
        float2 l2h = gather_rows2(lp, list_l, CNT_L_CONS);                               \
        ls  = fadd(fadd(ls, l2h.x), l2h.y);                                              \
        lsq = fadd(fadd(lsq, fmul(l2h.x, l2h.x)), fmul(l2h.y, l2h.y));                   \
        float dd0 = ffma(ren.x, hz0, ffma(rgn.x, hy0, fmul(rs, l2h.x)));                 \
        float dd1 = ffma(ren.y, hz1, ffma(rgn.y, hy1, fmul(rs, l2h.y)));                 \
        hz0 = ffma(DTc, dd0, hz0);                                                       \
        hz1 = ffma(DTc, dd1, hz1);                                                       \
        hy0 = ffma(DTc, hz0, hy0);                                                       \
        hy1 = ffma(DTc, hz1, hy1);                                                       \
        bool spk0 = (fsub(fsub(hy0, 1.0f), rf0) > 0.0f);                                 \
        bool spk1 = (fsub(fsub(hy1, 1.0f), rf1) > 0.0f);                                 \
        rf0 = ffma(rf0, refd, spk0 ? 1.0f : 0.0f);                                       \
        rf1 = ffma(rf1, refd, spk1 ? 1.0f : 0.0f);                                       \
        thrf += (spk0 ? 1 : 0) + (spk1 ? 1 : 0);                                         \
        {                                                                                \
            unsigned c0 = __ballot_sync(0xffffffffu, spk0);                              \
            unsigned c1 = __ballot_sync(0xffffffffu, spk1);                              \
            if (c0 | c1) {                                                               \
                int wn = __popc(c0) + __popc(c1);                                        \
                int base = 0;                                                            \
                if (lane == 0) base = atomicAdd(&CNT_S_PUB, wn);                         \
                base = __shfl_sync(0xffffffffu, base, 0);                                \
                int pre = base + __popc(c0 & lmask) + __popc(c1 & lmask);                \
                if (spk0) list_s[pre] = off0;                                            \
                if (spk1) list_s[pre + (spk0 ? 1 : 0)] = off1;                           \
            }                                                                            \
            if (wid == 15) { if (lane == 0) CNT_L_RST = 0; }                             \
        }                                                                                \
        __syncthreads();                                                                 \
    }

    for (int t = 0; t < L_; t += 2) {
        // even step (p=0,q=1)
        STEP_BODY(cntS1, cntL0, cntS0, cntL0, cntS0, cntL1, t)
        // odd step  (p=1,q=0)
        STEP_BODY(cntS0, cntL1, cntS1, cntL1, cntS1, cntL0, t + 1)
    }
#undef STEP_BODY

    // output hy
    {
        float2 o; o.x = hy0; o.y = hy1;
        ((float2*)(out + b * NH))[j] = o;
    }

    // ---------- block-level stat reductions (deterministic trees) ----------
    float r;
    r = block_reduce16((float)thrf, wid, lane, redf); if (j == 0) g_partials[b*8 + 0] = r;
    r = block_reduce16((float)tlif, wid, lane, redf); if (j == 0) g_partials[b*8 + 1] = r;
    r = block_reduce16(vs,  wid, lane, redf);         if (j == 0) g_partials[b*8 + 2] = r;
    r = block_reduce16(vsq, wid, lane, redf);         if (j == 0) g_partials[b*8 + 3] = r;
    r = block_reduce16(ls,  wid, lane, redf);         if (j == 0) g_partials[b*8 + 4] = r;
    r = block_reduce16(lsq, wid, lane, redf);         if (j == 0) g_partials[b*8 + 5] = r;
}

// parallel, deterministic finalize: 128 threads (one per batch), shuffle trees in double
__global__ void finalize_kernel(float* __restrict__ out)
{
    const int b    = threadIdx.x;          // 0..127
    const int wid  = b >> 5;
    const int lane = b & 31;
    __shared__ double sd[6][4];

    double val[6];
    #pragma unroll
    for (int s = 0; s < 6; s++) val[s] = (double)g_partials[b * 8 + s];

    #pragma unroll
    for (int s = 0; s < 6; s++) {
        double v = val[s];
        #pragma unroll
        for (int o = 16; o > 0; o >>= 1) v += __shfl_down_sync(0xffffffffu, v, o);
        if (lane == 0) sd[s][wid] = v;
    }
    __syncthreads();

    if (b == 0) {
        double tot[6];
        #pragma unroll
        for (int s = 0; s < 6; s++)
            tot[s] = (sd[s][0] + sd[s][1]) + (sd[s][2] + sd[s][3]);
        const double denom = (double)B_ * (double)L_ * (double)NH;
        float r_hrf = (float)(tot[0] / denom);
        float r_lif = (float)(tot[1] / denom);
        float vm    = (float)(tot[2] / denom);
        float vstd  = sqrtf((float)(tot[3] / denom) - vm * vm);
        float lm    = (float)(tot[4] / denom);
        float lstd  = sqrtf((float)(tot[5] / denom) - lm * lm);
        float* sc = out + B_ * NH;
        sc[0] = r_hrf;   // r_total (count_lif_spikes=False)
        sc[1] = r_hrf;
        sc[2] = r_lif;
        sc[3] = vm;
        sc[4] = vstd;
        sc[5] = lm;
        sc[6] = lstd;
    }
}

extern "C" void kernel_launch(void* const* d_in, const int* in_sizes, int n_in,
                              void* d_out, int out_size)
{
    const float* x       = (const float*)d_in[0];
    const float* x2h     = (const float*)d_in[1];
    const float* h2h     = (const float*)d_in[2];
    const float* bias    = (const float*)d_in[3];
    const float* lif2hrf = (const float*)d_in[4];
    const float* gamma   = (const float*)d_in[5];
    const float* eps     = (const float*)d_in[6];
    const float* sg      = (const float*)d_in[7];
    float* out = (float*)d_out;

    coesn_kernel<<<B_, TPB>>>(x, x2h, h2h, bias, lif2hrf, gamma, eps, sg, out);
    finalize_kernel<<<1, 128>>>(out);
}